// round 3
// baseline (speedup 1.0000x reference)
#include <cuda_runtime.h>

// Problem constants (fixed shapes from the reference)
#define E_DIM   1024
#define M_TOT   4096     // 2 * 2048 rows of x
#define SEQ     2048
#define NBATCH  32       // b * h
#define HD      64       // head dim

// Scratch for Q/K/V projections (48 MB total).
__device__ float g_Q[M_TOT * E_DIM];
__device__ float g_K[M_TOT * E_DIM];
__device__ float g_V[M_TOT * E_DIM];

// ---------------------------------------------------------------------------
// Helpers: tf32 rounding + m16n8k8 tf32 tensor-core MMA
// ---------------------------------------------------------------------------
__device__ __forceinline__ float f2tf32(float x) {
    unsigned u;
    asm("cvt.rna.tf32.f32 %0, %1;" : "=r"(u) : "f"(x));
    return __uint_as_float(u);
}

__device__ __forceinline__ void mma_tf32(float c[4], const unsigned a[4],
                                         const unsigned b[2]) {
    asm volatile(
        "mma.sync.aligned.m16n8k8.row.col.f32.tf32.tf32.f32 "
        "{%0,%1,%2,%3}, {%4,%5,%6,%7}, {%8,%9}, {%0,%1,%2,%3};"
        : "+f"(c[0]), "+f"(c[1]), "+f"(c[2]), "+f"(c[3])
        : "r"(a[0]), "r"(a[1]), "r"(a[2]), "r"(a[3]), "r"(b[0]), "r"(b[1]));
}

// ---------------------------------------------------------------------------
// Projection GEMM (tensor cores): C[M,N] = X[M,K] @ W[N,K]^T + bias[N]
// CTA tile 128x128, BK=32, 8 warps (2 x 4), warp tile 64x32.
// Smem tiles stored row-major [row][k] with stride 36 (36%32==4 ->
// fragment loads hit banks 4*(lane/4)+lane%4, all distinct).
// ---------------------------------------------------------------------------
#define P_LD 36

__global__ __launch_bounds__(256) void proj_kernel(
    const float* __restrict__ X,
    const float* __restrict__ Wq, const float* __restrict__ bq,
    const float* __restrict__ Wk, const float* __restrict__ bk,
    const float* __restrict__ Wv, const float* __restrict__ bv)
{
    const float* W;
    const float* bias;
    float* C;
    if (blockIdx.z == 0)      { W = Wq; bias = bq; C = g_Q; }
    else if (blockIdx.z == 1) { W = Wk; bias = bk; C = g_K; }
    else                      { W = Wv; bias = bv; C = g_V; }

    __shared__ float Xs[128 * P_LD];   // [m][k], tf32 values
    __shared__ float Ws[128 * P_LD];   // [n][k], tf32 values

    const int tid   = threadIdx.x;
    const int lane  = tid & 31;
    const int warp  = tid >> 5;
    const int warpM = warp >> 2;        // 0..1
    const int warpN = warp & 3;         // 0..3
    const int g     = lane >> 2;        // 0..7
    const int tg    = lane & 3;         // 0..3
    const int m0    = blockIdx.y * 128;
    const int n0    = blockIdx.x * 128;

    float acc[4][4][4];                 // [mi][nj][frag]
#pragma unroll
    for (int i = 0; i < 4; i++)
#pragma unroll
        for (int j = 0; j < 4; j++)
#pragma unroll
            for (int f = 0; f < 4; f++) acc[i][j][f] = 0.f;

    for (int k0 = 0; k0 < E_DIM; k0 += 32) {
        // Fill tiles: 128x32 floats each = 1024 float4 -> 4 per thread each.
#pragma unroll
        for (int r = 0; r < 4; r++) {
            int idx = tid + r * 256;        // 0..1023
            int row = idx >> 3;             // 0..127
            int c4  = (idx & 7) * 4;        // 0,4,...,28
            float4 v = *(const float4*)&X[(size_t)(m0 + row) * E_DIM + k0 + c4];
            float* dx = &Xs[row * P_LD + c4];
            dx[0] = f2tf32(v.x); dx[1] = f2tf32(v.y);
            dx[2] = f2tf32(v.z); dx[3] = f2tf32(v.w);
            float4 w = *(const float4*)&W[(size_t)(n0 + row) * E_DIM + k0 + c4];
            float* dw = &Ws[row * P_LD + c4];
            dw[0] = f2tf32(w.x); dw[1] = f2tf32(w.y);
            dw[2] = f2tf32(w.z); dw[3] = f2tf32(w.w);
        }
        __syncthreads();

#pragma unroll
        for (int kk = 0; kk < 4; kk++) {    // 4 k-steps of 8
            const int kb = kk * 8;
            unsigned a[4][4], b[4][2];
#pragma unroll
            for (int i = 0; i < 4; i++) {
                int row = warpM * 64 + i * 16;
                a[i][0] = __float_as_uint(Xs[(row + g)     * P_LD + kb + tg]);
                a[i][1] = __float_as_uint(Xs[(row + g + 8) * P_LD + kb + tg]);
                a[i][2] = __float_as_uint(Xs[(row + g)     * P_LD + kb + tg + 4]);
                a[i][3] = __float_as_uint(Xs[(row + g + 8) * P_LD + kb + tg + 4]);
            }
#pragma unroll
            for (int j = 0; j < 4; j++) {
                int n = warpN * 32 + j * 8;
                b[j][0] = __float_as_uint(Ws[(n + g) * P_LD + kb + tg]);
                b[j][1] = __float_as_uint(Ws[(n + g) * P_LD + kb + tg + 4]);
            }
#pragma unroll
            for (int i = 0; i < 4; i++)
#pragma unroll
                for (int j = 0; j < 4; j++)
                    mma_tf32(acc[i][j], a[i], b[j]);
        }
        __syncthreads();
    }

    // Epilogue: C-fragment layout c0:(g, tg*2) c1:+1 c2:(g+8, tg*2) c3:+1
#pragma unroll
    for (int i = 0; i < 4; i++) {
        int rbase = m0 + warpM * 64 + i * 16;
#pragma unroll
        for (int j = 0; j < 4; j++) {
            int col = n0 + warpN * 32 + j * 8 + tg * 2;
            float b0 = bias[col], b1 = bias[col + 1];
            float2* p0 = (float2*)&C[(size_t)(rbase + g) * E_DIM + col];
            *p0 = make_float2(acc[i][j][0] + b0, acc[i][j][1] + b1);
            float2* p1 = (float2*)&C[(size_t)(rbase + g + 8) * E_DIM + col];
            *p1 = make_float2(acc[i][j][2] + b0, acc[i][j][3] + b1);
        }
    }
}

// ---------------------------------------------------------------------------
// Attention (no softmax): O = (Q K^T * 0.125) @ V per batch, tensor cores.
// CTA = 128 q-rows of one batch; 8 warps each own 16 q-rows.
// Loop over kk chunks of 64:
//   Phase A: S[16][64] = Q_rows @ Kchunk^T   (mma, staged to smem per-warp)
//   Phase B: O[16][64] += S @ Vchunk         (mma, accumulators persistent)
// Smem strides: Qs/Ks/Ss = 68 (A/B frag loads conflict-free: 68%32==4),
//               Vs = 72 (k-major B frag loads conflict-free: 72%32==8).
// ---------------------------------------------------------------------------
#define A_LDQ 68
#define A_LDV 72

__global__ __launch_bounds__(256) void attn_kernel(float* __restrict__ out)
{
    const int b  = blockIdx.y;
    const int q0 = blockIdx.x * 128;
    const float* Q = g_Q + (size_t)b * SEQ * HD;
    const float* K = g_K + (size_t)b * SEQ * HD;
    const float* V = g_V + (size_t)b * SEQ * HD;
    float* O = out + (size_t)b * SEQ * HD;

    extern __shared__ float sm[];
    float* Qs = sm;                          // [128][A_LDQ]
    float* Ks = Qs + 128 * A_LDQ;            // [64][A_LDQ]
    float* Vs = Ks + 64 * A_LDQ;             // [64][A_LDV]
    float* Ss = Vs + 64 * A_LDV;             // [128][A_LDQ]

    const int tid  = threadIdx.x;
    const int lane = tid & 31;
    const int warp = tid >> 5;               // 0..7 -> q rows [warp*16, +16)
    const int g    = lane >> 2;
    const int tg   = lane & 3;
    const int base = warp * 16;
    const float scale = 0.125f;

    // Load Q tile (tf32): 128x64 = 2048 float4 -> 8 per thread.
#pragma unroll
    for (int r = 0; r < 8; r++) {
        int idx = tid + r * 256;
        int row = idx >> 4;
        int c4  = (idx & 15) * 4;
        float4 v = *(const float4*)&Q[(size_t)(q0 + row) * HD + c4];
        float* d = &Qs[row * A_LDQ + c4];
        d[0] = f2tf32(v.x); d[1] = f2tf32(v.y);
        d[2] = f2tf32(v.z); d[3] = f2tf32(v.w);
    }

    float accO[8][4];
#pragma unroll
    for (int j = 0; j < 8; j++)
#pragma unroll
        for (int f = 0; f < 4; f++) accO[j][f] = 0.f;

    for (int k0 = 0; k0 < SEQ; k0 += 64) {
        __syncthreads();   // prev Phase B done with Vs; (iter0: orders Qs fill)
        // Load K,V chunks (tf32): each 64x64 = 1024 float4 -> 4 per thread.
#pragma unroll
        for (int r = 0; r < 4; r++) {
            int idx = tid + r * 256;
            int row = idx >> 4;
            int c4  = (idx & 15) * 4;
            float4 kv = *(const float4*)&K[(size_t)(k0 + row) * HD + c4];
            float* dk = &Ks[row * A_LDQ + c4];
            dk[0] = f2tf32(kv.x); dk[1] = f2tf32(kv.y);
            dk[2] = f2tf32(kv.z); dk[3] = f2tf32(kv.w);
            float4 vv = *(const float4*)&V[(size_t)(k0 + row) * HD + c4];
            float* dv = &Vs[row * A_LDV + c4];
            dv[0] = f2tf32(vv.x); dv[1] = f2tf32(vv.y);
            dv[2] = f2tf32(vv.z); dv[3] = f2tf32(vv.w);
        }
        __syncthreads();

        // ---- Phase A: S[16][64] = Q[16][64] @ K[64][64]^T
        float accS[8][4];
#pragma unroll
        for (int j = 0; j < 8; j++)
#pragma unroll
            for (int f = 0; f < 4; f++) accS[j][f] = 0.f;

#pragma unroll
        for (int ks = 0; ks < 8; ks++) {     // depth d = ks*8..+8
            const int kb = ks * 8;
            unsigned a[4];
            a[0] = __float_as_uint(Qs[(base + g)     * A_LDQ + kb + tg]);
            a[1] = __float_as_uint(Qs[(base + g + 8) * A_LDQ + kb + tg]);
            a[2] = __float_as_uint(Qs[(base + g)     * A_LDQ + kb + tg + 4]);
            a[3] = __float_as_uint(Qs[(base + g + 8) * A_LDQ + kb + tg + 4]);
#pragma unroll
            for (int j = 0; j < 8; j++) {    // kk-local tile
                unsigned bb[2];
                bb[0] = __float_as_uint(Ks[(j * 8 + g) * A_LDQ + kb + tg]);
                bb[1] = __float_as_uint(Ks[(j * 8 + g) * A_LDQ + kb + tg + 4]);
                mma_tf32(accS[j], a, bb);
            }
        }

        // Stage S (scaled, tf32) in this warp's own smem rows; warp-local.
#pragma unroll
        for (int j = 0; j < 8; j++) {
            int c = j * 8 + tg * 2;
            Ss[(base + g)     * A_LDQ + c]     = f2tf32(accS[j][0] * scale);
            Ss[(base + g)     * A_LDQ + c + 1] = f2tf32(accS[j][1] * scale);
            Ss[(base + g + 8) * A_LDQ + c]     = f2tf32(accS[j][2] * scale);
            Ss[(base + g + 8) * A_LDQ + c + 1] = f2tf32(accS[j][3] * scale);
        }
        __syncwarp();

        // ---- Phase B: O[16][64] += S[16][64] @ V[64][64]
#pragma unroll
        for (int ks = 0; ks < 8; ks++) {     // k = kk-local = ks*8..+8
            const int kb = ks * 8;
            unsigned a[4];
            a[0] = __float_as_uint(Ss[(base + g)     * A_LDQ + kb + tg]);
            a[1] = __float_as_uint(Ss[(base + g + 8) * A_LDQ + kb + tg]);
            a[2] = __float_as_uint(Ss[(base + g)     * A_LDQ + kb + tg + 4]);
            a[3] = __float_as_uint(Ss[(base + g + 8) * A_LDQ + kb + tg + 4]);
#pragma unroll
            for (int j = 0; j < 8; j++) {    // d tile
                unsigned bb[2];
                bb[0] = __float_as_uint(Vs[(kb + tg)     * A_LDV + j * 8 + g]);
                bb[1] = __float_as_uint(Vs[(kb + tg + 4) * A_LDV + j * 8 + g]);
                mma_tf32(accO[j], a, bb);
            }
        }
        __syncwarp();   // Phase B reads of Ss done before next chunk rewrites
    }

    // Epilogue: write O rows [q0+base, +16)
#pragma unroll
    for (int j = 0; j < 8; j++) {
        int c = j * 8 + tg * 2;
        float2* p0 = (float2*)&O[(size_t)(q0 + base + g) * HD + c];
        *p0 = make_float2(accO[j][0], accO[j][1]);
        float2* p1 = (float2*)&O[(size_t)(q0 + base + g + 8) * HD + c];
        *p1 = make_float2(accO[j][2], accO[j][3]);
    }
}

// ---------------------------------------------------------------------------
extern "C" void kernel_launch(void* const* d_in, const int* in_sizes, int n_in,
                              void* d_out, int out_size)
{
    const float* x  = (const float*)d_in[0];
    const float* Wq = (const float*)d_in[1];
    const float* bq = (const float*)d_in[2];
    const float* Wk = (const float*)d_in[3];
    const float* bk = (const float*)d_in[4];
    const float* Wv = (const float*)d_in[5];
    const float* bv = (const float*)d_in[6];
    float* out = (float*)d_out;

    const int attn_smem =
        (128 * A_LDQ + 64 * A_LDQ + 64 * A_LDV + 128 * A_LDQ) * (int)sizeof(float);
    cudaFuncSetAttribute(attn_kernel,
                         cudaFuncAttributeMaxDynamicSharedMemorySize,
                         attn_smem);

    dim3 pgrid(E_DIM / 128, M_TOT / 128, 3);
    proj_kernel<<<pgrid, 256>>>(x, Wq, bq, Wk, bk, Wv, bv);

    dim3 agrid(SEQ / 128, NBATCH);
    attn_kernel<<<agrid, 256, attn_smem>>>(out);
}

// round 4
// speedup vs baseline: 2.2081x; 2.2081x over previous
#include <cuda_runtime.h>
#include <cuda_fp16.h>

#define E_DIM   1024
#define M_TOT   4096
#define SEQ     2048
#define NBATCH  32
#define HD      64

// half-precision scratch
__device__ __half g_xh[M_TOT * E_DIM];
__device__ __half g_Wh[3 * E_DIM * E_DIM];
__device__ __half g_Qh[M_TOT * E_DIM];   // pre-scaled by 0.125
__device__ __half g_Kh[M_TOT * E_DIM];
__device__ __half g_Vh[M_TOT * E_DIM];

__device__ __forceinline__ unsigned su32(const void* p) {
    return (unsigned)__cvta_generic_to_shared(p);
}
#define CPA16(d, s) \
    asm volatile("cp.async.cg.shared.global [%0],[%1],16;" :: "r"(d), "l"(s))
#define CP_COMMIT() asm volatile("cp.async.commit_group;")
#define CP_WAIT(n)  asm volatile("cp.async.wait_group %0;" :: "n"(n))

#define LDSM_X4(r0, r1, r2, r3, p) \
    asm volatile("ldmatrix.sync.aligned.m8n8.x4.shared.b16 {%0,%1,%2,%3},[%4];" \
                 : "=r"(r0), "=r"(r1), "=r"(r2), "=r"(r3) : "r"(p))
#define LDSM_X4T(r0, r1, r2, r3, p) \
    asm volatile("ldmatrix.sync.aligned.m8n8.x4.trans.shared.b16 {%0,%1,%2,%3},[%4];" \
                 : "=r"(r0), "=r"(r1), "=r"(r2), "=r"(r3) : "r"(p))

#define MMA16(c, a, b0_, b1_) \
    asm volatile("mma.sync.aligned.m16n8k16.row.col.f32.f16.f16.f32 " \
                 "{%0,%1,%2,%3},{%4,%5,%6,%7},{%8,%9},{%0,%1,%2,%3};" \
                 : "+f"((c)[0]), "+f"((c)[1]), "+f"((c)[2]), "+f"((c)[3]) \
                 : "r"((a)[0]), "r"((a)[1]), "r"((a)[2]), "r"((a)[3]), \
                   "r"(b0_), "r"(b1_))

// ---------------------------------------------------------------------------
// cvt: f32 -> f16 for x, Wq, Wk, Wv
// ---------------------------------------------------------------------------
__global__ void cvt_kernel(const float* __restrict__ x,
                           const float* __restrict__ wq,
                           const float* __restrict__ wk,
                           const float* __restrict__ wv)
{
    const int NX = (M_TOT * E_DIM) / 4;
    const int NW = (E_DIM * E_DIM) / 4;
    int i = blockIdx.x * 256 + threadIdx.x;
    int stride = gridDim.x * 256;
    for (; i < NX + 3 * NW; i += stride) {
        const float* s; __half* d; int off;
        if (i < NX)               { s = x;  d = g_xh;                     off = i; }
        else if (i < NX + NW)     { s = wq; d = g_Wh;                     off = i - NX; }
        else if (i < NX + 2 * NW) { s = wk; d = g_Wh + E_DIM * E_DIM;     off = i - NX - NW; }
        else                      { s = wv; d = g_Wh + 2 * E_DIM * E_DIM; off = i - NX - 2 * NW; }
        float4 v = ((const float4*)s)[off];
        ((__half2*)d)[2 * off]     = __floats2half2_rn(v.x, v.y);
        ((__half2*)d)[2 * off + 1] = __floats2half2_rn(v.z, v.w);
    }
}

// ---------------------------------------------------------------------------
// Projection: C[M,N] = X @ W^T + bias  (half in, half out; Q scaled 0.125)
// CTA 128x128, BK=32, double-buffered cp.async, 8 warps (2x4), warp 64x32.
// ---------------------------------------------------------------------------
#define PJ_LD 40   // halfs per smem row (80B)

__global__ __launch_bounds__(256, 2) void proj_kernel(
    const float* __restrict__ bq, const float* __restrict__ bk,
    const float* __restrict__ bv)
{
    const __half* W; const float* bias; __half* C; float oscale;
    if (blockIdx.z == 0)      { W = g_Wh;                     bias = bq; C = g_Qh; oscale = 0.125f; }
    else if (blockIdx.z == 1) { W = g_Wh + E_DIM * E_DIM;     bias = bk; C = g_Kh; oscale = 1.0f; }
    else                      { W = g_Wh + 2 * E_DIM * E_DIM; bias = bv; C = g_Vh; oscale = 1.0f; }

    __shared__ __half Xs[2][128 * PJ_LD];
    __shared__ __half Ws[2][128 * PJ_LD];

    const int tid  = threadIdx.x, lane = tid & 31;
    const int warp = tid >> 5, warpM = warp >> 2, warpN = warp & 3;
    const int g = lane >> 2, tg = lane & 3;
    const int quad = lane >> 3, rr = lane & 7;
    const int m0 = blockIdx.y * 128, n0 = blockIdx.x * 128;

    float acc[4][4][4];
#pragma unroll
    for (int i = 0; i < 4; i++)
#pragma unroll
        for (int j = 0; j < 4; j++)
#pragma unroll
            for (int f = 0; f < 4; f++) acc[i][j][f] = 0.f;

#define PJ_ISSUE(buf, k0)                                                     \
    do {                                                                      \
        _Pragma("unroll")                                                     \
        for (int t = 0; t < 2; t++) {                                         \
            int seg = tid + t * 256;                                          \
            int row = seg >> 2, s4 = seg & 3;                                 \
            CPA16(su32(&Xs[buf][row * PJ_LD + s4 * 8]),                       \
                  &g_xh[(size_t)(m0 + row) * E_DIM + (k0) + s4 * 8]);         \
            CPA16(su32(&Ws[buf][row * PJ_LD + s4 * 8]),                       \
                  &W[(size_t)(n0 + row) * E_DIM + (k0) + s4 * 8]);            \
        }                                                                     \
    } while (0)

    PJ_ISSUE(0, 0);
    CP_COMMIT();

    for (int kt = 0; kt < 32; kt++) {
        int buf = kt & 1;
        __syncthreads();
        if (kt < 31) { PJ_ISSUE(buf ^ 1, (kt + 1) * 32); CP_COMMIT(); CP_WAIT(1); }
        else         { CP_WAIT(0); }
        __syncthreads();

#pragma unroll
        for (int ks = 0; ks < 2; ks++) {
            const int kb = ks * 16;
            unsigned a[4][4];
#pragma unroll
            for (int i = 0; i < 4; i++) {
                int row = warpM * 64 + i * 16 + ((quad & 1) << 3) + rr;
                int col = kb + ((quad >> 1) << 3);
                LDSM_X4(a[i][0], a[i][1], a[i][2], a[i][3],
                        su32(&Xs[buf][row * PJ_LD + col]));
            }
#pragma unroll
            for (int jj = 0; jj < 2; jj++) {
                int nrow = warpN * 32 + jj * 16 + ((quad >> 1) << 3) + rr;
                int col  = kb + ((quad & 1) << 3);
                unsigned b0, b1, b2, b3;
                LDSM_X4(b0, b1, b2, b3, su32(&Ws[buf][nrow * PJ_LD + col]));
#pragma unroll
                for (int i = 0; i < 4; i++) {
                    MMA16(acc[i][2 * jj],     a[i], b0, b1);
                    MMA16(acc[i][2 * jj + 1], a[i], b2, b3);
                }
            }
        }
    }

#pragma unroll
    for (int j = 0; j < 4; j++) {
        int col = n0 + warpN * 32 + j * 8 + tg * 2;
        float b0 = bias[col], b1 = bias[col + 1];
#pragma unroll
        for (int i = 0; i < 4; i++) {
            int rbase = m0 + warpM * 64 + i * 16;
            *(__half2*)&C[(size_t)(rbase + g) * E_DIM + col] =
                __floats2half2_rn((acc[i][j][0] + b0) * oscale,
                                  (acc[i][j][1] + b1) * oscale);
            *(__half2*)&C[(size_t)(rbase + g + 8) * E_DIM + col] =
                __floats2half2_rn((acc[i][j][2] + b0) * oscale,
                                  (acc[i][j][3] + b1) * oscale);
        }
    }
}

// ---------------------------------------------------------------------------
// Attention: O = (Q*0.125 @ K^T) @ V, fp16 mma, cp.async double buffer.
// CTA = 128 q-rows; 8 warps x 16 rows. Q frags hoisted; Ss reuses Qs.
// ---------------------------------------------------------------------------
#define AT_LD 72   // halfs per row (144B)

__global__ __launch_bounds__(256, 2) void attn_kernel(float* __restrict__ out)
{
    const int b  = blockIdx.y;
    const int q0 = blockIdx.x * 128;
    const __half* Qg = g_Qh + (size_t)b * SEQ * HD;
    const __half* Kg = g_Kh + (size_t)b * SEQ * HD;
    const __half* Vg = g_Vh + (size_t)b * SEQ * HD;
    float* O = out + (size_t)b * SEQ * HD;

    extern __shared__ __half sh[];
    __half* Qs = sh;                       // [128][72]; becomes Ss after hoist
    __half* Ks = sh + 128 * AT_LD;         // [2][64][72]
    __half* Vs = Ks + 2 * 64 * AT_LD;      // [2][64][72]
    __half* Ss = Qs;

    const int tid  = threadIdx.x, lane = tid & 31, warp = tid >> 5;
    const int g = lane >> 2, tg = lane & 3;
    const int quad = lane >> 3, rr = lane & 7;
    const int base = warp * 16;

#define KV_ISSUE(buf, k0)                                                     \
    do {                                                                      \
        _Pragma("unroll")                                                     \
        for (int t = 0; t < 2; t++) {                                         \
            int seg = tid + t * 256;                                          \
            int row = seg >> 3, s8 = seg & 7;                                 \
            CPA16(su32(&Ks[(buf) * 64 * AT_LD + row * AT_LD + s8 * 8]),       \
                  &Kg[(size_t)((k0) + row) * HD + s8 * 8]);                   \
            CPA16(su32(&Vs[(buf) * 64 * AT_LD + row * AT_LD + s8 * 8]),       \
                  &Vg[(size_t)((k0) + row) * HD + s8 * 8]);                   \
        }                                                                     \
    } while (0)

    // Prologue: Q tile (group 1), then K/V chunk 0 (group 2)
#pragma unroll
    for (int t = 0; t < 4; t++) {
        int seg = tid + t * 256;
        int row = seg >> 3, s8 = seg & 7;
        CPA16(su32(&Qs[row * AT_LD + s8 * 8]),
              &Qg[(size_t)(q0 + row) * HD + s8 * 8]);
    }
    CP_COMMIT();
    KV_ISSUE(0, 0);
    CP_COMMIT();
    CP_WAIT(1);                 // Q resident (chunk0 may still be in flight)
    __syncthreads();

    // Hoist Q fragments (scale folded into g_Qh)
    unsigned aq[4][4];
#pragma unroll
    for (int ks = 0; ks < 4; ks++) {
        int row = base + ((quad & 1) << 3) + rr;
        int col = ks * 16 + ((quad >> 1) << 3);
        LDSM_X4(aq[ks][0], aq[ks][1], aq[ks][2], aq[ks][3],
                su32(&Qs[row * AT_LD + col]));
    }

    float accO[8][4];
#pragma unroll
    for (int j = 0; j < 8; j++)
#pragma unroll
        for (int f = 0; f < 4; f++) accO[j][f] = 0.f;

    for (int c = 0; c < 32; c++) {
        int buf = c & 1;
        __syncthreads();                    // buf^1 free; Qs hoist done (c==0)
        if (c < 31) { KV_ISSUE(buf ^ 1, (c + 1) * 64); CP_COMMIT(); CP_WAIT(1); }
        else        { CP_WAIT(0); }
        __syncthreads();                    // publish chunk c
        const __half* Kb = Ks + buf * 64 * AT_LD;
        const __half* Vb = Vs + buf * 64 * AT_LD;

        // Phase A: S[16][64] = Q @ Kchunk^T
        float accS[8][4];
#pragma unroll
        for (int j = 0; j < 8; j++)
#pragma unroll
            for (int f = 0; f < 4; f++) accS[j][f] = 0.f;

#pragma unroll
        for (int ks = 0; ks < 4; ks++) {
            const int kb = ks * 16;
#pragma unroll
            for (int jj = 0; jj < 4; jj++) {
                int nrow = jj * 16 + ((quad >> 1) << 3) + rr;
                int col  = kb + ((quad & 1) << 3);
                unsigned b0, b1, b2, b3;
                LDSM_X4(b0, b1, b2, b3, su32(&Kb[nrow * AT_LD + col]));
                MMA16(accS[2 * jj],     aq[ks], b0, b1);
                MMA16(accS[2 * jj + 1], aq[ks], b2, b3);
            }
        }

        // Stage S as half (warp-local rows of Ss)
#pragma unroll
        for (int j = 0; j < 8; j++) {
            int cc = j * 8 + tg * 2;
            *(__half2*)&Ss[(base + g) * AT_LD + cc] =
                __floats2half2_rn(accS[j][0], accS[j][1]);
            *(__half2*)&Ss[(base + g + 8) * AT_LD + cc] =
                __floats2half2_rn(accS[j][2], accS[j][3]);
        }
        __syncwarp();

        // Phase B: O[16][64] += S @ Vchunk
#pragma unroll
        for (int ks = 0; ks < 4; ks++) {
            const int kb = ks * 16;
            unsigned as[4];
            int arow = base + ((quad & 1) << 3) + rr;
            int acol = kb + ((quad >> 1) << 3);
            LDSM_X4(as[0], as[1], as[2], as[3],
                    su32(&Ss[arow * AT_LD + acol]));
#pragma unroll
            for (int jj = 0; jj < 4; jj++) {
                int krow = kb + ((quad & 1) << 3) + rr;
                int ncol = jj * 16 + ((quad >> 1) << 3);
                unsigned v0, v1, v2, v3;
                LDSM_X4T(v0, v1, v2, v3, su32(&Vb[krow * AT_LD + ncol]));
                MMA16(accO[2 * jj],     as, v0, v1);
                MMA16(accO[2 * jj + 1], as, v2, v3);
            }
        }
        __syncwarp();   // Ss reads done before next iteration rewrites
    }

    // Epilogue
#pragma unroll
    for (int j = 0; j < 8; j++) {
        int cc = j * 8 + tg * 2;
        *(float2*)&O[(size_t)(q0 + base + g) * HD + cc] =
            make_float2(accO[j][0], accO[j][1]);
        *(float2*)&O[(size_t)(q0 + base + g + 8) * HD + cc] =
            make_float2(accO[j][2], accO[j][3]);
    }
}

// ---------------------------------------------------------------------------
extern "C" void kernel_launch(void* const* d_in, const int* in_sizes, int n_in,
                              void* d_out, int out_size)
{
    const float* x  = (const float*)d_in[0];
    const float* Wq = (const float*)d_in[1];
    const float* bq = (const float*)d_in[2];
    const float* Wk = (const float*)d_in[3];
    const float* bk = (const float*)d_in[4];
    const float* Wv = (const float*)d_in[5];
    const float* bv = (const float*)d_in[6];
    float* out = (float*)d_out;

    const int attn_smem = (128 + 2 * 64 + 2 * 64) * AT_LD * (int)sizeof(__half);
    cudaFuncSetAttribute(attn_kernel,
                         cudaFuncAttributeMaxDynamicSharedMemorySize,
                         attn_smem);

    cvt_kernel<<<4096, 256>>>(x, Wq, Wk, Wv);

    dim3 pgrid(E_DIM / 128, M_TOT / 128, 3);
    proj_kernel<<<pgrid, 256>>>(bq, bk, bv);

    dim3 agrid(SEQ / 128, NBATCH);
    attn_kernel<<<agrid, 256, attn_smem>>>(out);
}

// round 5
// speedup vs baseline: 3.7810x; 1.7123x over previous
#include <cuda_runtime.h>
#include <cuda_fp16.h>

#define E_DIM   1024
#define M_TOT   4096
#define SEQ     2048
#define NBATCH  32
#define HD      64

// half-precision scratch
__device__ __half g_xh[M_TOT * E_DIM];
__device__ __half g_Wh[3 * E_DIM * E_DIM];
__device__ __half g_Qh[M_TOT * E_DIM];
__device__ __half g_Kh[M_TOT * E_DIM];
__device__ __half g_Vh[M_TOT * E_DIM];
__device__ __half g_Th[NBATCH * HD * HD];   // T = 0.125 * K^T V, per batch

__device__ __forceinline__ unsigned su32(const void* p) {
    return (unsigned)__cvta_generic_to_shared(p);
}
#define CPA16(d, s) \
    asm volatile("cp.async.cg.shared.global [%0],[%1],16;" :: "r"(d), "l"(s))
#define CP_COMMIT() asm volatile("cp.async.commit_group;")
#define CP_WAIT(n)  asm volatile("cp.async.wait_group %0;" :: "n"(n))

#define LDSM_X4(r0, r1, r2, r3, p) \
    asm volatile("ldmatrix.sync.aligned.m8n8.x4.shared.b16 {%0,%1,%2,%3},[%4];" \
                 : "=r"(r0), "=r"(r1), "=r"(r2), "=r"(r3) : "r"(p))
#define LDSM_X4T(r0, r1, r2, r3, p) \
    asm volatile("ldmatrix.sync.aligned.m8n8.x4.trans.shared.b16 {%0,%1,%2,%3},[%4];" \
                 : "=r"(r0), "=r"(r1), "=r"(r2), "=r"(r3) : "r"(p))

#define MMA16(c, a, b0_, b1_) \
    asm volatile("mma.sync.aligned.m16n8k16.row.col.f32.f16.f16.f32 " \
                 "{%0,%1,%2,%3},{%4,%5,%6,%7},{%8,%9},{%0,%1,%2,%3};" \
                 : "+f"((c)[0]), "+f"((c)[1]), "+f"((c)[2]), "+f"((c)[3]) \
                 : "r"((a)[0]), "r"((a)[1]), "r"((a)[2]), "r"((a)[3]), \
                   "r"(b0_), "r"(b1_))

// ---------------------------------------------------------------------------
// cvt: f32 -> f16 for x, Wq, Wk, Wv
// ---------------------------------------------------------------------------
__global__ void cvt_kernel(const float* __restrict__ x,
                           const float* __restrict__ wq,
                           const float* __restrict__ wk,
                           const float* __restrict__ wv)
{
    const int NX = (M_TOT * E_DIM) / 4;
    const int NW = (E_DIM * E_DIM) / 4;
    int i = blockIdx.x * 256 + threadIdx.x;
    int stride = gridDim.x * 256;
    for (; i < NX + 3 * NW; i += stride) {
        const float* s; __half* d; int off;
        if (i < NX)               { s = x;  d = g_xh;                     off = i; }
        else if (i < NX + NW)     { s = wq; d = g_Wh;                     off = i - NX; }
        else if (i < NX + 2 * NW) { s = wk; d = g_Wh + E_DIM * E_DIM;     off = i - NX - NW; }
        else                      { s = wv; d = g_Wh + 2 * E_DIM * E_DIM; off = i - NX - 2 * NW; }
        float4 v = ((const float4*)s)[off];
        ((__half2*)d)[2 * off]     = __floats2half2_rn(v.x, v.y);
        ((__half2*)d)[2 * off + 1] = __floats2half2_rn(v.z, v.w);
    }
}

// ---------------------------------------------------------------------------
// Projection: C[M,N] = X @ W^T + bias  (half in, half out)
// CTA 128x128, BK=32, double-buffered cp.async, 8 warps (2x4), warp 64x32.
// ---------------------------------------------------------------------------
#define PJ_LD 40

__global__ __launch_bounds__(256, 2) void proj_kernel(
    const float* __restrict__ bq, const float* __restrict__ bk,
    const float* __restrict__ bv)
{
    const __half* W; const float* bias; __half* C;
    if (blockIdx.z == 0)      { W = g_Wh;                     bias = bq; C = g_Qh; }
    else if (blockIdx.z == 1) { W = g_Wh + E_DIM * E_DIM;     bias = bk; C = g_Kh; }
    else                      { W = g_Wh + 2 * E_DIM * E_DIM; bias = bv; C = g_Vh; }

    __shared__ __half Xs[2][128 * PJ_LD];
    __shared__ __half Ws[2][128 * PJ_LD];

    const int tid  = threadIdx.x, lane = tid & 31;
    const int warp = tid >> 5, warpM = warp >> 2, warpN = warp & 3;
    const int g = lane >> 2, tg = lane & 3;
    const int quad = lane >> 3, rr = lane & 7;
    const int m0 = blockIdx.y * 128, n0 = blockIdx.x * 128;

    float acc[4][4][4];
#pragma unroll
    for (int i = 0; i < 4; i++)
#pragma unroll
        for (int j = 0; j < 4; j++)
#pragma unroll
            for (int f = 0; f < 4; f++) acc[i][j][f] = 0.f;

#define PJ_ISSUE(buf, k0)                                                     \
    do {                                                                      \
        _Pragma("unroll")                                                     \
        for (int t = 0; t < 2; t++) {                                         \
            int seg = tid + t * 256;                                          \
            int row = seg >> 2, s4 = seg & 3;                                 \
            CPA16(su32(&Xs[buf][row * PJ_LD + s4 * 8]),                       \
                  &g_xh[(size_t)(m0 + row) * E_DIM + (k0) + s4 * 8]);         \
            CPA16(su32(&Ws[buf][row * PJ_LD + s4 * 8]),                       \
                  &W[(size_t)(n0 + row) * E_DIM + (k0) + s4 * 8]);            \
        }                                                                     \
    } while (0)

    PJ_ISSUE(0, 0);
    CP_COMMIT();

    for (int kt = 0; kt < 32; kt++) {
        int buf = kt & 1;
        __syncthreads();
        if (kt < 31) { PJ_ISSUE(buf ^ 1, (kt + 1) * 32); CP_COMMIT(); CP_WAIT(1); }
        else         { CP_WAIT(0); }
        __syncthreads();

#pragma unroll
        for (int ks = 0; ks < 2; ks++) {
            const int kb = ks * 16;
            unsigned a[4][4];
#pragma unroll
            for (int i = 0; i < 4; i++) {
                int row = warpM * 64 + i * 16 + ((quad & 1) << 3) + rr;
                int col = kb + ((quad >> 1) << 3);
                LDSM_X4(a[i][0], a[i][1], a[i][2], a[i][3],
                        su32(&Xs[buf][row * PJ_LD + col]));
            }
#pragma unroll
            for (int jj = 0; jj < 2; jj++) {
                int nrow = warpN * 32 + jj * 16 + ((quad >> 1) << 3) + rr;
                int col  = kb + ((quad & 1) << 3);
                unsigned b0, b1, b2, b3;
                LDSM_X4(b0, b1, b2, b3, su32(&Ws[buf][nrow * PJ_LD + col]));
#pragma unroll
                for (int i = 0; i < 4; i++) {
                    MMA16(acc[i][2 * jj],     a[i], b0, b1);
                    MMA16(acc[i][2 * jj + 1], a[i], b2, b3);
                }
            }
        }
    }

#pragma unroll
    for (int j = 0; j < 4; j++) {
        int col = n0 + warpN * 32 + j * 8 + tg * 2;
        float b0 = bias[col], b1 = bias[col + 1];
#pragma unroll
        for (int i = 0; i < 4; i++) {
            int rbase = m0 + warpM * 64 + i * 16;
            *(__half2*)&C[(size_t)(rbase + g) * E_DIM + col] =
                __floats2half2_rn(acc[i][j][0] + b0, acc[i][j][1] + b1);
            *(__half2*)&C[(size_t)(rbase + g + 8) * E_DIM + col] =
                __floats2half2_rn(acc[i][j][2] + b0, acc[i][j][3] + b1);
        }
    }
}

// ---------------------------------------------------------------------------
// kv_kernel: T[b] = 0.125 * K[b]^T @ V[b]   (64x64 per batch, fp32 accum)
// One CTA per batch (32 CTAs). 8 warps: warp w -> m-half (w>>2)*32 (dk),
// n-strip (w&3)*16 (dv). A = K^T via ldmatrix.trans, B = V via ldmatrix.trans.
// ---------------------------------------------------------------------------
#define KV_LD 72

__global__ __launch_bounds__(256) void kv_kernel()
{
    const int b = blockIdx.x;
    const __half* Kg = g_Kh + (size_t)b * SEQ * HD;
    const __half* Vg = g_Vh + (size_t)b * SEQ * HD;

    __shared__ __half Ks[2][64 * KV_LD];
    __shared__ __half Vs[2][64 * KV_LD];

    const int tid  = threadIdx.x, lane = tid & 31, warp = tid >> 5;
    const int g = lane >> 2, tg = lane & 3;
    const int quad = lane >> 3, rr = lane & 7;
    const int mh = (warp >> 2) * 32;   // dk base (2 m16 tiles)
    const int nb = (warp & 3) * 16;    // dv base (1 n16 = 2 n8 tiles)

    float accT[2][2][4];
#pragma unroll
    for (int mt = 0; mt < 2; mt++)
#pragma unroll
        for (int jn = 0; jn < 2; jn++)
#pragma unroll
            for (int f = 0; f < 4; f++) accT[mt][jn][f] = 0.f;

#define KV2_ISSUE(buf, k0)                                                    \
    do {                                                                      \
        _Pragma("unroll")                                                     \
        for (int t = 0; t < 2; t++) {                                         \
            int seg = tid + t * 256;                                          \
            int row = seg >> 3, s8 = seg & 7;                                 \
            CPA16(su32(&Ks[buf][row * KV_LD + s8 * 8]),                       \
                  &Kg[(size_t)((k0) + row) * HD + s8 * 8]);                   \
            CPA16(su32(&Vs[buf][row * KV_LD + s8 * 8]),                       \
                  &Vg[(size_t)((k0) + row) * HD + s8 * 8]);                   \
        }                                                                     \
    } while (0)

    KV2_ISSUE(0, 0);
    CP_COMMIT();

    for (int c = 0; c < 32; c++) {
        int buf = c & 1;
        __syncthreads();
        if (c < 31) { KV2_ISSUE(buf ^ 1, (c + 1) * 64); CP_COMMIT(); CP_WAIT(1); }
        else        { CP_WAIT(0); }
        __syncthreads();

#pragma unroll
        for (int ks = 0; ks < 4; ks++) {
            const int sb = ks * 16;
            // A-frags = (K^T) m16k16 tiles: trans load, rows = s, cols = dk
            unsigned a[2][4];
#pragma unroll
            for (int mt = 0; mt < 2; mt++) {
                int row = sb + ((quad >> 1) << 3) + rr;
                int col = mh + mt * 16 + ((quad & 1) << 3);
                LDSM_X4T(a[mt][0], a[mt][1], a[mt][2], a[mt][3],
                         su32(&Ks[buf][row * KV_LD + col]));
            }
            // B-frags = V k16n16: trans load, rows = s, cols = dv
            int vrow = sb + ((quad & 1) << 3) + rr;
            int vcol = nb + ((quad >> 1) << 3);
            unsigned v0, v1, v2, v3;
            LDSM_X4T(v0, v1, v2, v3, su32(&Vs[buf][vrow * KV_LD + vcol]));
#pragma unroll
            for (int mt = 0; mt < 2; mt++) {
                MMA16(accT[mt][0], a[mt], v0, v1);
                MMA16(accT[mt][1], a[mt], v2, v3);
            }
        }
    }

    // Epilogue: T[dk][dv] as half, scaled by 0.125
    __half* T = g_Th + b * HD * HD;
#pragma unroll
    for (int mt = 0; mt < 2; mt++) {
        int dk0 = mh + mt * 16;
#pragma unroll
        for (int jn = 0; jn < 2; jn++) {
            int dv = nb + jn * 8 + tg * 2;
            *(__half2*)&T[(dk0 + g) * HD + dv] =
                __floats2half2_rn(accT[mt][jn][0] * 0.125f,
                                  accT[mt][jn][1] * 0.125f);
            *(__half2*)&T[(dk0 + g + 8) * HD + dv] =
                __floats2half2_rn(accT[mt][jn][2] * 0.125f,
                                  accT[mt][jn][3] * 0.125f);
        }
    }
}

// ---------------------------------------------------------------------------
// qt_kernel: O[b] = Q[b] @ T[b]   ([2048,64] @ [64,64], fp32 out)
// CTA = 128 q-rows; 8 warps x 16 rows. grid (16, 32).
// ---------------------------------------------------------------------------
#define QT_LD 72

__global__ __launch_bounds__(256) void qt_kernel(float* __restrict__ out)
{
    const int b  = blockIdx.y;
    const int q0 = blockIdx.x * 128;
    const __half* Qg = g_Qh + (size_t)b * SEQ * HD;
    const __half* Tg = g_Th + (size_t)b * HD * HD;
    float* O = out + (size_t)b * SEQ * HD;

    __shared__ __half Qs[128 * QT_LD];
    __shared__ __half Ts[64 * QT_LD];

    const int tid  = threadIdx.x, lane = tid & 31, warp = tid >> 5;
    const int g = lane >> 2, tg = lane & 3;
    const int quad = lane >> 3, rr = lane & 7;
    const int base = warp * 16;

    // Fill Q tile (1024 segs -> 4/thread) and T (512 segs -> 2/thread)
#pragma unroll
    for (int t = 0; t < 4; t++) {
        int seg = tid + t * 256;
        int row = seg >> 3, s8 = seg & 7;
        CPA16(su32(&Qs[row * QT_LD + s8 * 8]),
              &Qg[(size_t)(q0 + row) * HD + s8 * 8]);
    }
#pragma unroll
    for (int t = 0; t < 2; t++) {
        int seg = tid + t * 256;
        int row = seg >> 3, s8 = seg & 7;
        CPA16(su32(&Ts[row * QT_LD + s8 * 8]), &Tg[row * HD + s8 * 8]);
    }
    CP_COMMIT();
    CP_WAIT(0);
    __syncthreads();

    float accO[8][4];
#pragma unroll
    for (int j = 0; j < 8; j++)
#pragma unroll
        for (int f = 0; f < 4; f++) accO[j][f] = 0.f;

#pragma unroll
    for (int ks = 0; ks < 4; ks++) {
        const int kb = ks * 16;
        unsigned a[4];
        int arow = base + ((quad & 1) << 3) + rr;
        int acol = kb + ((quad >> 1) << 3);
        LDSM_X4(a[0], a[1], a[2], a[3], su32(&Qs[arow * QT_LD + acol]));
#pragma unroll
        for (int jj = 0; jj < 4; jj++) {
            int krow = kb + ((quad & 1) << 3) + rr;
            int ncol = jj * 16 + ((quad >> 1) << 3);
            unsigned v0, v1, v2, v3;
            LDSM_X4T(v0, v1, v2, v3, su32(&Ts[krow * QT_LD + ncol]));
            MMA16(accO[2 * jj],     a, v0, v1);
            MMA16(accO[2 * jj + 1], a, v2, v3);
        }
    }

#pragma unroll
    for (int j = 0; j < 8; j++) {
        int cc = j * 8 + tg * 2;
        *(float2*)&O[(size_t)(q0 + base + g) * HD + cc] =
            make_float2(accO[j][0], accO[j][1]);
        *(float2*)&O[(size_t)(q0 + base + g + 8) * HD + cc] =
            make_float2(accO[j][2], accO[j][3]);
    }
}

// ---------------------------------------------------------------------------
extern "C" void kernel_launch(void* const* d_in, const int* in_sizes, int n_in,
                              void* d_out, int out_size)
{
    const float* x  = (const float*)d_in[0];
    const float* Wq = (const float*)d_in[1];
    const float* bq = (const float*)d_in[2];
    const float* Wk = (const float*)d_in[3];
    const float* bk = (const float*)d_in[4];
    const float* Wv = (const float*)d_in[5];
    const float* bv = (const float*)d_in[6];
    float* out = (float*)d_out;

    cvt_kernel<<<4096, 256>>>(x, Wq, Wk, Wv);

    dim3 pgrid(E_DIM / 128, M_TOT / 128, 3);
    proj_kernel<<<pgrid, 256>>>(bq, bk, bv);

    kv_kernel<<<NBATCH, 256>>>();

    dim3 qgrid(SEQ / 128, NBATCH);
    qt_kernel<<<qgrid, 256>>>(out);
}

// round 7
// speedup vs baseline: 4.8907x; 1.2935x over previous
#include <cuda_runtime.h>
#include <cuda_fp16.h>

#define E_DIM   1024
#define M_TOT   4096
#define SEQ     2048
#define NBATCH  32
#define HD      64

// half-precision scratch
__device__ __half g_xh[M_TOT * E_DIM];
__device__ __half g_Wh[3 * E_DIM * E_DIM];   // Wq | Wk | Wv stacked: [3072,1024]
__device__ __half g_Qh[M_TOT * E_DIM];
__device__ __half g_Kh[M_TOT * E_DIM];
__device__ __half g_Vh[M_TOT * E_DIM];
__device__ float  g_Tp[NBATCH * 4 * HD * HD]; // partial K^T V per (batch, chunk)

__device__ __forceinline__ unsigned su32(const void* p) {
    return (unsigned)__cvta_generic_to_shared(p);
}
#define CPA16(d, s) \
    asm volatile("cp.async.cg.shared.global [%0],[%1],16;" :: "r"(d), "l"(s))
#define CP_COMMIT() asm volatile("cp.async.commit_group;")
#define CP_WAIT(n)  asm volatile("cp.async.wait_group %0;" :: "n"(n))

#define LDSM_X4(r0, r1, r2, r3, p) \
    asm volatile("ldmatrix.sync.aligned.m8n8.x4.shared.b16 {%0,%1,%2,%3},[%4];" \
                 : "=r"(r0), "=r"(r1), "=r"(r2), "=r"(r3) : "r"(p))
#define LDSM_X4T(r0, r1, r2, r3, p) \
    asm volatile("ldmatrix.sync.aligned.m8n8.x4.trans.shared.b16 {%0,%1,%2,%3},[%4];" \
                 : "=r"(r0), "=r"(r1), "=r"(r2), "=r"(r3) : "r"(p))

#define MMA16(c, a, b0_, b1_) \
    asm volatile("mma.sync.aligned.m16n8k16.row.col.f32.f16.f16.f32 " \
                 "{%0,%1,%2,%3},{%4,%5,%6,%7},{%8,%9},{%0,%1,%2,%3};" \
                 : "+f"((c)[0]), "+f"((c)[1]), "+f"((c)[2]), "+f"((c)[3]) \
                 : "r"((a)[0]), "r"((a)[1]), "r"((a)[2]), "r"((a)[3]), \
                   "r"(b0_), "r"(b1_))

// ---------------------------------------------------------------------------
// cvt: f32 -> f16 for x, Wq, Wk, Wv
// ---------------------------------------------------------------------------
__global__ void cvt_kernel(const float* __restrict__ x,
                           const float* __restrict__ wq,
                           const float* __restrict__ wk,
                           const float* __restrict__ wv)
{
    const int NX = (M_TOT * E_DIM) / 4;
    const int NW = (E_DIM * E_DIM) / 4;
    int i = blockIdx.x * 256 + threadIdx.x;
    int stride = gridDim.x * 256;
    for (; i < NX + 3 * NW; i += stride) {
        const float* s; __half* d; int off;
        if (i < NX)               { s = x;  d = g_xh;                     off = i; }
        else if (i < NX + NW)     { s = wq; d = g_Wh;                     off = i - NX; }
        else if (i < NX + 2 * NW) { s = wk; d = g_Wh + E_DIM * E_DIM;     off = i - NX - NW; }
        else                      { s = wv; d = g_Wh + 2 * E_DIM * E_DIM; off = i - NX - 2 * NW; }
        float4 v = ((const float4*)s)[off];
        ((__half2*)d)[2 * off]     = __floats2half2_rn(v.x, v.y);
        ((__half2*)d)[2 * off + 1] = __floats2half2_rn(v.z, v.w);
    }
}

// ---------------------------------------------------------------------------
// Projection: C[4096,3072] = X[4096,1024] @ Wcat[3072,1024]^T + bias
// CTA 128x128, BK=64, THREE-stage cp.async pipeline, ONE sync per k-tile.
// 8 warps (2x4), warp tile 64x32. grid (24, 32).
// ---------------------------------------------------------------------------
#define PJ_LD   72                        // halfs per smem row (144B)
#define PJ_STG  ((128 + 128) * PJ_LD)     // halfs per stage
#define PJ_SMEM (3 * PJ_STG * (int)sizeof(__half))   // 110592 B

__global__ __launch_bounds__(256, 2) void proj_kernel(
    const float* __restrict__ bq, const float* __restrict__ bk,
    const float* __restrict__ bv)
{
    extern __shared__ __half sh[];

    const int tid  = threadIdx.x, lane = tid & 31;
    const int warp = tid >> 5, warpM = warp >> 2, warpN = warp & 3;
    const int g = lane >> 2, tg = lane & 3;
    const int quad = lane >> 3, rr = lane & 7;
    const int m0 = blockIdx.y * 128;
    const int n0 = blockIdx.x * 128;      // 0..3071 across Wq|Wk|Wv

    float acc[4][4][4];
#pragma unroll
    for (int i = 0; i < 4; i++)
#pragma unroll
        for (int j = 0; j < 4; j++)
#pragma unroll
            for (int f = 0; f < 4; f++) acc[i][j][f] = 0.f;

    // Fill one 64-wide k-stage: X 128 rows + W 128 rows, 144B rows,
    // 1024 chunks each -> 4 per thread per matrix.
#define PJ_FILL(st, k0)                                                       \
    do {                                                                      \
        __half* Xs = sh + (st) * PJ_STG;                                      \
        __half* Ws = Xs + 128 * PJ_LD;                                        \
        _Pragma("unroll")                                                     \
        for (int t = 0; t < 4; t++) {                                         \
            int seg = tid + t * 256;                                          \
            int row = seg >> 3, c16 = seg & 7;                                \
            CPA16(su32(Xs + row * PJ_LD + c16 * 8),                           \
                  &g_xh[(size_t)(m0 + row) * E_DIM + (k0) + c16 * 8]);        \
        }                                                                     \
        _Pragma("unroll")                                                     \
        for (int t = 0; t < 4; t++) {                                         \
            int seg = tid + t * 256;                                          \
            int row = seg >> 3, c16 = seg & 7;                                \
            CPA16(su32(Ws + row * PJ_LD + c16 * 8),                           \
                  &g_Wh[(size_t)(n0 + row) * E_DIM + (k0) + c16 * 8]);        \
        }                                                                     \
        CP_COMMIT();                                                          \
    } while (0)

    PJ_FILL(0, 0);
    PJ_FILL(1, 64);

    const int NKT = E_DIM / 64;           // 16
    for (int kt = 0; kt < NKT; kt++) {
        const int st = kt % 3;
        if (kt < NKT - 1) { CP_WAIT(1); } else { CP_WAIT(0); }
        __syncthreads();                  // stage kt visible; stage (kt+2)%3 free

        const __half* Xs = sh + st * PJ_STG;
        const __half* Ws = Xs + 128 * PJ_LD;

#pragma unroll
        for (int ks = 0; ks < 4; ks++) {
            const int kb = ks * 16;
            unsigned a[4][4];
#pragma unroll
            for (int i = 0; i < 4; i++) {
                int row = warpM * 64 + i * 16 + ((quad & 1) << 3) + rr;
                int col = kb + ((quad >> 1) << 3);
                LDSM_X4(a[i][0], a[i][1], a[i][2], a[i][3],
                        su32(Xs + row * PJ_LD + col));
            }
#pragma unroll
            for (int jj = 0; jj < 2; jj++) {
                int nrow = warpN * 32 + jj * 16 + ((quad >> 1) << 3) + rr;
                int col  = kb + ((quad & 1) << 3);
                unsigned b0, b1, b2, b3;
                LDSM_X4(b0, b1, b2, b3, su32(Ws + nrow * PJ_LD + col));
#pragma unroll
                for (int i = 0; i < 4; i++) {
                    MMA16(acc[i][2 * jj],     a[i], b0, b1);
                    MMA16(acc[i][2 * jj + 1], a[i], b2, b3);
                }
            }
        }

        if (kt + 2 < NKT) PJ_FILL((kt + 2) % 3, (kt + 2) * 64);
    }

    // Epilogue: select output tensor by which third of N this tile is in.
    const int which = n0 >> 10;
    const int nbase = n0 & 1023;
    const float* bias = (which == 0) ? bq : (which == 1) ? bk : bv;
    __half* C = (which == 0) ? g_Qh : (which == 1) ? g_Kh : g_Vh;

#pragma unroll
    for (int j = 0; j < 4; j++) {
        int col = nbase + warpN * 32 + j * 8 + tg * 2;
        float b0 = bias[col], b1 = bias[col + 1];
#pragma unroll
        for (int i = 0; i < 4; i++) {
            int rbase = m0 + warpM * 64 + i * 16;
            *(__half2*)&C[(size_t)(rbase + g) * E_DIM + col] =
                __floats2half2_rn(acc[i][j][0] + b0, acc[i][j][1] + b1);
            *(__half2*)&C[(size_t)(rbase + g + 8) * E_DIM + col] =
                __floats2half2_rn(acc[i][j][2] + b0, acc[i][j][3] + b1);
        }
    }
}

// ---------------------------------------------------------------------------
// kv_kernel: partial T[b,ch] = K[b, ch*512:+512]^T @ V[same]  (fp32 out)
// grid (4, 32) = 128 CTAs. 8 warps: warp w -> dk half (w>>2)*32, dv strip
// (w&3)*16. Scale 0.125 deferred to the reduce in qt_kernel.
// ---------------------------------------------------------------------------
#define KV_LD 72

__global__ __launch_bounds__(256) void kv_kernel()
{
    const int ch = blockIdx.x;            // 0..3
    const int b  = blockIdx.y;            // 0..31
    const __half* Kg = g_Kh + (size_t)b * SEQ * HD + (size_t)ch * 512 * HD;
    const __half* Vg = g_Vh + (size_t)b * SEQ * HD + (size_t)ch * 512 * HD;

    __shared__ __half Ks[2][64 * KV_LD];
    __shared__ __half Vs[2][64 * KV_LD];

    const int tid  = threadIdx.x, lane = tid & 31, warp = tid >> 5;
    const int g = lane >> 2, tg = lane & 3;
    const int quad = lane >> 3, rr = lane & 7;
    const int mh = (warp >> 2) * 32;
    const int nb = (warp & 3) * 16;

    float accT[2][2][4];
#pragma unroll
    for (int mt = 0; mt < 2; mt++)
#pragma unroll
        for (int jn = 0; jn < 2; jn++)
#pragma unroll
            for (int f = 0; f < 4; f++) accT[mt][jn][f] = 0.f;

#define KV2_ISSUE(buf, k0)                                                    \
    do {                                                                      \
        _Pragma("unroll")                                                     \
        for (int t = 0; t < 2; t++) {                                         \
            int seg = tid + t * 256;                                          \
            int row = seg >> 3, s8 = seg & 7;                                 \
            CPA16(su32(&Ks[buf][row * KV_LD + s8 * 8]),                       \
                  &Kg[(size_t)((k0) + row) * HD + s8 * 8]);                   \
            CPA16(su32(&Vs[buf][row * KV_LD + s8 * 8]),                       \
                  &Vg[(size_t)((k0) + row) * HD + s8 * 8]);                   \
        }                                                                     \
        CP_COMMIT();                                                          \
    } while (0)

    KV2_ISSUE(0, 0);

    for (int c = 0; c < 8; c++) {
        int buf = c & 1;
        __syncthreads();
        if (c < 7) { KV2_ISSUE(buf ^ 1, (c + 1) * 64); CP_WAIT(1); }
        else       { CP_WAIT(0); }
        __syncthreads();

#pragma unroll
        for (int ks = 0; ks < 4; ks++) {
            const int sb = ks * 16;
            unsigned a[2][4];
#pragma unroll
            for (int mt = 0; mt < 2; mt++) {
                int row = sb + ((quad >> 1) << 3) + rr;
                int col = mh + mt * 16 + ((quad & 1) << 3);
                LDSM_X4T(a[mt][0], a[mt][1], a[mt][2], a[mt][3],
                         su32(&Ks[buf][row * KV_LD + col]));
            }
            int vrow = sb + ((quad & 1) << 3) + rr;
            int vcol = nb + ((quad >> 1) << 3);
            unsigned v0, v1, v2, v3;
            LDSM_X4T(v0, v1, v2, v3, su32(&Vs[buf][vrow * KV_LD + vcol]));
#pragma unroll
            for (int mt = 0; mt < 2; mt++) {
                MMA16(accT[mt][0], a[mt], v0, v1);
                MMA16(accT[mt][1], a[mt], v2, v3);
            }
        }
    }

    float* Tp = g_Tp + ((size_t)(b * 4 + ch)) * HD * HD;
#pragma unroll
    for (int mt = 0; mt < 2; mt++) {
        int dk0 = mh + mt * 16;
#pragma unroll
        for (int jn = 0; jn < 2; jn++) {
            int dv = nb + jn * 8 + tg * 2;
            *(float2*)&Tp[(dk0 + g) * HD + dv] =
                make_float2(accT[mt][jn][0], accT[mt][jn][1]);
            *(float2*)&Tp[(dk0 + g + 8) * HD + dv] =
                make_float2(accT[mt][jn][2], accT[mt][jn][3]);
        }
    }
}

// ---------------------------------------------------------------------------
// qt_kernel: O[b] = Q[b] @ (0.125 * sum_ch Tp[b,ch])   fp32 out
// CTA = 128 q-rows; reduce of the 4 partials folded into the prologue.
// ---------------------------------------------------------------------------
#define QT_LD 72

__global__ __launch_bounds__(256) void qt_kernel(float* __restrict__ out)
{
    const int b  = blockIdx.y;
    const int q0 = blockIdx.x * 128;
    const __half* Qg = g_Qh + (size_t)b * SEQ * HD;
    float* O = out + (size_t)b * SEQ * HD;

    __shared__ __half Qs[128 * QT_LD];
    __shared__ __half Ts[64 * QT_LD];

    const int tid  = threadIdx.x, lane = tid & 31, warp = tid >> 5;
    const int g = lane >> 2, tg = lane & 3;
    const int quad = lane >> 3, rr = lane & 7;
    const int base = warp * 16;

    // Q tile via cp.async (overlaps with the T reduce below)
#pragma unroll
    for (int t = 0; t < 4; t++) {
        int seg = tid + t * 256;
        int row = seg >> 3, s8 = seg & 7;
        CPA16(su32(&Qs[row * QT_LD + s8 * 8]),
              &Qg[(size_t)(q0 + row) * HD + s8 * 8]);
    }
    CP_COMMIT();

    // Reduce 4 partials -> Ts (half), scaled by 0.125
    {
        const float4* P4 = (const float4*)(g_Tp + (size_t)b * 4 * HD * HD);
#pragma unroll
        for (int t = 0; t < 4; t++) {
            int idx = tid + t * 256;          // 0..1023 float4 slots
            float4 p0 = P4[idx];
            float4 p1 = P4[idx + 1024];
            float4 p2 = P4[idx + 2048];
            float4 p3 = P4[idx + 3072];
            float sx = (p0.x + p1.x + p2.x + p3.x) * 0.125f;
            float sy = (p0.y + p1.y + p2.y + p3.y) * 0.125f;
            float sz = (p0.z + p1.z + p2.z + p3.z) * 0.125f;
            float sw = (p0.w + p1.w + p2.w + p3.w) * 0.125f;
            int row = idx >> 4, col = (idx & 15) * 4;
            *(__half2*)&Ts[row * QT_LD + col]     = __floats2half2_rn(sx, sy);
            *(__half2*)&Ts[row * QT_LD + col + 2] = __floats2half2_rn(sz, sw);
        }
    }

    CP_WAIT(0);
    __syncthreads();

    float accO[8][4];
#pragma unroll
    for (int j = 0; j < 8; j++)
#pragma unroll
        for (int f = 0; f < 4; f++) accO[j][f] = 0.f;

#pragma unroll
    for (int ks = 0; ks < 4; ks++) {
        const int kb = ks * 16;
        unsigned a[4];
        int arow = base + ((quad & 1) << 3) + rr;
        int acol = kb + ((quad >> 1) << 3);
        LDSM_X4(a[0], a[1], a[2], a[3], su32(&Qs[arow * QT_LD + acol]));
#pragma unroll
        for (int jj = 0; jj < 4; jj++) {
            int krow = kb + ((quad & 1) << 3) + rr;
            int ncol = jj * 16 + ((quad >> 1) << 3);
            unsigned v0, v1, v2, v3;
            LDSM_X4T(v0, v1, v2, v3, su32(&Ts[krow * QT_LD + ncol]));
            MMA16(accO[2 * jj],     a, v0, v1);
            MMA16(accO[2 * jj + 1], a, v2, v3);
        }
    }

#pragma unroll
    for (int j = 0; j < 8; j++) {
        int cc = j * 8 + tg * 2;
        *(float2*)&O[(size_t)(q0 + base + g) * HD + cc] =
            make_float2(accO[j][0], accO[j][1]);
        *(float2*)&O[(size_t)(q0 + base + g + 8) * HD + cc] =
            make_float2(accO[j][2], accO[j][3]);
    }
}

// ---------------------------------------------------------------------------
extern "C" void kernel_launch(void* const* d_in, const int* in_sizes, int n_in,
                              void* d_out, int out_size)
{
    const float* x  = (const float*)d_in[0];
    const float* Wq = (const float*)d_in[1];
    const float* bq = (const float*)d_in[2];
    const float* Wk = (const float*)d_in[3];
    const float* bk = (const float*)d_in[4];
    const float* Wv = (const float*)d_in[5];
    const float* bv = (const float*)d_in[6];
    float* out = (float*)d_out;

    cudaFuncSetAttribute(proj_kernel,
                         cudaFuncAttributeMaxDynamicSharedMemorySize,
                         PJ_SMEM);

    cvt_kernel<<<4096, 256>>>(x, Wq, Wk, Wv);

    dim3 pgrid(3 * E_DIM / 128, M_TOT / 128);
    proj_kernel<<<pgrid, 256, PJ_SMEM>>>(bq, bk, bv);

    kv_kernel<<<dim3(4, NBATCH), 256>>>();

    dim3 qgrid(SEQ / 128, NBATCH);
    qt_kernel<<<qgrid, 256>>>(out);
}